// round 1
// baseline (speedup 1.0000x reference)
#include <cuda_runtime.h>
#include <math.h>

#define NN 50000
#define NE 800000
#define CH 64
#define SEQL 8

// ---------------- static scratch (allowed: __device__ globals) ----------------
__device__ float g_deg[NN];
__device__ float g_dinv[NN];
__device__ int   g_cnt[NN];
__device__ int   g_off[NN + 1];
__device__ int   g_cur[NN];
__device__ int   g_col[NE];
__device__ float g_w[NE];
__device__ float g_T1[(size_t)NN * CH];
__device__ float g_T2[(size_t)NN * CH];
__device__ float g_GX[(size_t)NN * 192];
__device__ float g_Z [(size_t)NN * CH];
__device__ float g_HR[(size_t)NN * CH];
__device__ float g_H0[(size_t)NN * CH];   // stays zero (zero-initialized at load, never written)

// ---------------- setup kernels ----------------
__global__ void k_zero_setup() {
    int i = blockIdx.x * blockDim.x + threadIdx.x;
    if (i < NN) { g_deg[i] = 0.f; g_cnt[i] = 0; g_cur[i] = 0; }
}

__global__ void k_deg(const int* __restrict__ ei, const float* __restrict__ ew) {
    int e = blockIdx.x * blockDim.x + threadIdx.x;
    if (e < NE) {
        int r = ei[e], c = ei[NE + e];
        if (r != c) atomicAdd(&g_deg[r], ew[e]);
    }
}

__global__ void k_dinv() {
    int i = blockIdx.x * blockDim.x + threadIdx.x;
    if (i < NN) {
        float d = g_deg[i];
        g_dinv[i] = d > 0.f ? rsqrtf(d) : 0.f;
    }
}

__global__ void k_count(const int* __restrict__ ei) {
    int e = blockIdx.x * blockDim.x + threadIdx.x;
    if (e < NE) atomicAdd(&g_cnt[ei[e]], 1);
}

__global__ void k_scan() {
    __shared__ int sh[1024];
    int tid = threadIdx.x;
    const int chunk = (NN + 1023) / 1024;   // 49
    int base = tid * chunk;
    int s = 0;
    for (int i = 0; i < chunk; i++) {
        int idx = base + i;
        if (idx < NN) s += g_cnt[idx];
    }
    sh[tid] = s;
    __syncthreads();
    for (int d = 1; d < 1024; d <<= 1) {
        int v = (tid >= d) ? sh[tid - d] : 0;
        __syncthreads();
        sh[tid] += v;
        __syncthreads();
    }
    int run = (tid == 0) ? 0 : sh[tid - 1];
    for (int i = 0; i < chunk; i++) {
        int idx = base + i;
        if (idx < NN) { g_off[idx] = run; run += g_cnt[idx]; }
    }
    if (tid == 0) g_off[NN] = sh[1023];
}

__global__ void k_scatter(const int* __restrict__ ei, const float* __restrict__ ew) {
    int e = blockIdx.x * blockDim.x + threadIdx.x;
    if (e < NE) {
        int r = ei[e], c = ei[NE + e];
        float w = (r == c) ? 0.f : ew[e];
        float wn = -w * g_dinv[r] * g_dinv[c];
        int pos = g_off[r] + atomicAdd(&g_cur[r], 1);
        g_col[pos] = c;
        g_w[pos]   = wn;
    }
}

// ---------------- SpMM: out = alpha * (S @ vin) + beta * base ----------------
// One warp per row; each lane owns channels (lane, lane+32).
__global__ void k_spmm(const float* __restrict__ vin, const float* __restrict__ base,
                       float alpha, float beta, float* __restrict__ out) {
    int warp = (blockIdx.x * blockDim.x + threadIdx.x) >> 5;
    int lane = threadIdx.x & 31;
    if (warp >= NN) return;
    int s = g_off[warp], e = g_off[warp + 1];
    float a0 = 0.f, a1 = 0.f;
    float b0 = 0.f, b1 = 0.f;   // second accumulator pair for ILP
    int j = s;
    for (; j + 1 < e; j += 2) {
        int   c0 = g_col[j],   c1 = g_col[j + 1];
        float w0 = g_w[j],     w1 = g_w[j + 1];
        const float* v0 = vin + (size_t)c0 * CH;
        const float* v1 = vin + (size_t)c1 * CH;
        a0 += w0 * v0[lane];
        a1 += w0 * v0[lane + 32];
        b0 += w1 * v1[lane];
        b1 += w1 * v1[lane + 32];
    }
    if (j < e) {
        int c = g_col[j]; float w = g_w[j];
        const float* v = vin + (size_t)c * CH;
        a0 += w * v[lane];
        a1 += w * v[lane + 32];
    }
    a0 += b0; a1 += b1;
    size_t o = (size_t)warp * CH + lane;
    float r0 = alpha * a0, r1 = alpha * a1;
    if (beta != 0.f) {
        r0 += beta * base[o];
        r1 += beta * base[o + 32];
    }
    out[o]      = r0;
    out[o + 32] = r1;
}

// ---------------- GEMM: acc = A0@W0 + A1@W1 + A2@W2 (N x 64), fused epilogues -----------
// BM=128 rows/block, 64 output cols, 128 threads, 8x8 per-thread tiles, BK=32.
#define BM 128
#define BK 32

// EPI 0: out[r*outStride + outOff + c] = acc + bias[c]                        (GX write)
// EPI 1: Z = sigmoid(acc + bias + GX[r,c])          -> out (Zbuf)
// EPI 2: R = sigmoid(acc + bias + GX[r,64+c]); out = H*R                      (HRbuf)
// EPI 3: Ht = tanh(acc + bias + GX[r,128+c]); out = Z*H + (1-Z)*Ht            (States slice)
template <int EPI>
__global__ void k_gemm(const float* __restrict__ A0, const float* __restrict__ A1,
                       const float* __restrict__ A2,
                       const float* __restrict__ W0, const float* __restrict__ W1,
                       const float* __restrict__ W2,
                       const float* __restrict__ bias,
                       const float* __restrict__ GX,
                       const float* __restrict__ H, const float* __restrict__ Z,
                       float* __restrict__ out, int outStride, int outOff) {
    __shared__ float As[BK][BM + 4];   // k-major, padded row stride = 132 floats
    __shared__ float Bs[BK][CH];

    int tid = threadIdx.x;
    int tx = tid & 7;         // 0..7  -> output cols tx*8..tx*8+7
    int ty = tid >> 3;        // 0..15 -> rows ty*8..ty*8+7
    int rb = blockIdx.x * BM;

    float acc[8][8];
#pragma unroll
    for (int i = 0; i < 8; i++)
#pragma unroll
        for (int jj = 0; jj < 8; jj++) acc[i][jj] = 0.f;

    const float* Asrc[3] = {A0, A1, A2};
    const float* Wsrc[3] = {W0, W1, W2};

    for (int s = 0; s < 3; s++) {
        const float* A = Asrc[s];
        const float* W = Wsrc[s];
#pragma unroll
        for (int h = 0; h < 2; h++) {
            // load A tile: rows rb..rb+127, cols h*32..h*32+31 (A is N x 64 row-major)
#pragma unroll
            for (int i = 0; i < 8; i++) {
                int idx = tid + i * 128;      // 0..1023 float4 slots
                int row = idx >> 3;           // 8 float4 per row
                int kq  = idx & 7;
                float4 v = make_float4(0.f, 0.f, 0.f, 0.f);
                int gr = rb + row;
                if (gr < NN) v = *(const float4*)(A + (size_t)gr * CH + h * BK + kq * 4);
                As[kq * 4 + 0][row] = v.x;
                As[kq * 4 + 1][row] = v.y;
                As[kq * 4 + 2][row] = v.z;
                As[kq * 4 + 3][row] = v.w;
            }
            // load W tile: rows h*32..h*32+31, all 64 cols
#pragma unroll
            for (int i = 0; i < 4; i++) {
                int idx = tid + i * 128;      // 0..511 float4 slots
                int kr = idx >> 4;            // 16 float4 per row
                int cq = idx & 15;
                float4 v = *(const float4*)(W + (size_t)(h * BK + kr) * CH + cq * 4);
                *(float4*)&Bs[kr][cq * 4] = v;
            }
            __syncthreads();
#pragma unroll
            for (int k = 0; k < BK; k++) {
                float a[8], b[8];
                *(float4*)&a[0] = *(const float4*)&As[k][ty * 8];
                *(float4*)&a[4] = *(const float4*)&As[k][ty * 8 + 4];
                *(float4*)&b[0] = *(const float4*)&Bs[k][tx * 8];
                *(float4*)&b[4] = *(const float4*)&Bs[k][tx * 8 + 4];
#pragma unroll
                for (int i = 0; i < 8; i++)
#pragma unroll
                    for (int jj = 0; jj < 8; jj++) acc[i][jj] += a[i] * b[jj];
            }
            __syncthreads();
        }
    }

    // epilogue
#pragma unroll
    for (int i = 0; i < 8; i++) {
        int r = rb + ty * 8 + i;
        if (r >= NN) continue;
#pragma unroll
        for (int jj = 0; jj < 8; jj++) {
            int c = tx * 8 + jj;
            float v = acc[i][jj] + bias[c];
            if (EPI == 0) {
                out[(size_t)r * outStride + outOff + c] = v;
            } else if (EPI == 1) {
                v += GX[(size_t)r * 192 + c];
                out[(size_t)r * CH + c] = 1.f / (1.f + expf(-v));
            } else if (EPI == 2) {
                v += GX[(size_t)r * 192 + 64 + c];
                float R = 1.f / (1.f + expf(-v));
                out[(size_t)r * CH + c] = H[(size_t)r * CH + c] * R;
            } else {
                v += GX[(size_t)r * 192 + 128 + c];
                float ht = tanhf(v);
                float z  = Z[(size_t)r * CH + c];
                float hp = H[(size_t)r * CH + c];
                out[(size_t)r * CH + c] = z * hp + (1.f - z) * ht;
            }
        }
    }
}

__global__ void k_copy(const float* __restrict__ src, float* __restrict__ dst, int n) {
    int i = blockIdx.x * blockDim.x + threadIdx.x;
    if (i < n) dst[i] = src[i];
}

// ---------------- host side ----------------
extern "C" void kernel_launch(void* const* d_in, const int* in_sizes, int n_in,
                              void* d_out, int out_size) {
    const float* X    = (const float*)d_in[0];
    const int*   ei   = (const int*)  d_in[1];
    const float* ew   = (const float*)d_in[2];
    const float* W_xz = (const float*)d_in[3];
    const float* b_xz = (const float*)d_in[4];
    const float* W_hz = (const float*)d_in[5];
    const float* b_hz = (const float*)d_in[6];
    const float* W_xr = (const float*)d_in[7];
    const float* b_xr = (const float*)d_in[8];
    const float* W_hr = (const float*)d_in[9];
    const float* b_hr = (const float*)d_in[10];
    const float* W_xh = (const float*)d_in[11];
    const float* b_xh = (const float*)d_in[12];
    const float* W_hh = (const float*)d_in[13];
    const float* b_hh = (const float*)d_in[14];
    float* out = (float*)d_out;

    float *pT1, *pT2, *pGX, *pZ, *pHR, *pH0;
    cudaGetSymbolAddress((void**)&pT1, g_T1);
    cudaGetSymbolAddress((void**)&pT2, g_T2);
    cudaGetSymbolAddress((void**)&pGX, g_GX);
    cudaGetSymbolAddress((void**)&pZ,  g_Z);
    cudaGetSymbolAddress((void**)&pHR, g_HR);
    cudaGetSymbolAddress((void**)&pH0, g_H0);

    const int NB_NODE = (NN + 255) / 256;
    const int NB_EDGE = (NE + 255) / 256;
    const int NB_SPMM = (NN * 32 + 255) / 256;
    const int NB_GEMM = (NN + BM - 1) / BM;

    // graph normalization + CSR build
    k_zero_setup<<<NB_NODE, 256>>>();
    k_deg<<<NB_EDGE, 256>>>(ei, ew);
    k_dinv<<<NB_NODE, 256>>>();
    k_count<<<NB_EDGE, 256>>>(ei);
    k_scan<<<1, 1024>>>();
    k_scatter<<<NB_EDGE, 256>>>(ei, ew);

    const size_t SL = (size_t)NN * CH;   // per-timestep slice
    const int WS = CH * CH;              // 4096: per-k weight slice

    for (int t = 0; t < SEQL; t++) {
        const float* Xt = X + (size_t)t * SL;
        const float* Hp = (t == 0) ? pH0 : (out + (size_t)(t - 1) * SL);
        float* Ot = out + (size_t)t * SL;

        // X Chebyshev basis + GX = [Xb]@Wx_{z,r,h} + b_x*
        k_spmm<<<NB_SPMM, 256>>>(Xt, Xt, 1.f, 0.f, pT1);
        k_spmm<<<NB_SPMM, 256>>>(pT1, Xt, 2.f, -1.f, pT2);
        k_gemm<0><<<NB_GEMM, 128>>>(Xt, pT1, pT2, W_xz, W_xz + WS, W_xz + 2 * WS,
                                    b_xz, pGX, Hp, pZ, pGX, 192, 0);
        k_gemm<0><<<NB_GEMM, 128>>>(Xt, pT1, pT2, W_xr, W_xr + WS, W_xr + 2 * WS,
                                    b_xr, pGX, Hp, pZ, pGX, 192, 64);
        k_gemm<0><<<NB_GEMM, 128>>>(Xt, pT1, pT2, W_xh, W_xh + WS, W_xh + 2 * WS,
                                    b_xh, pGX, Hp, pZ, pGX, 192, 128);

        // H Chebyshev basis; Z and R (fused sigmoid, R fused into HR = H*R)
        k_spmm<<<NB_SPMM, 256>>>(Hp, Hp, 1.f, 0.f, pT1);
        k_spmm<<<NB_SPMM, 256>>>(pT1, Hp, 2.f, -1.f, pT2);
        k_gemm<1><<<NB_GEMM, 128>>>(Hp, pT1, pT2, W_hz, W_hz + WS, W_hz + 2 * WS,
                                    b_hz, pGX, Hp, pZ, pZ, CH, 0);
        k_gemm<2><<<NB_GEMM, 128>>>(Hp, pT1, pT2, W_hr, W_hr + WS, W_hr + 2 * WS,
                                    b_hr, pGX, Hp, pZ, pHR, CH, 0);

        // HR Chebyshev basis; candidate state + GRU combine -> States[t]
        k_spmm<<<NB_SPMM, 256>>>(pHR, pHR, 1.f, 0.f, pT1);
        k_spmm<<<NB_SPMM, 256>>>(pT1, pHR, 2.f, -1.f, pT2);
        k_gemm<3><<<NB_GEMM, 128>>>(pHR, pT1, pT2, W_hh, W_hh + WS, W_hh + 2 * WS,
                                    b_hh, pGX, Hp, pZ, Ot, CH, 0);
    }

    // Hlast = States[:, -1]
    if (out_size >= (int)((SEQL + 1) * SL)) {
        int n = (int)SL;
        k_copy<<<(n + 255) / 256, 256>>>(out + (size_t)(SEQL - 1) * SL,
                                         out + (size_t)SEQL * SL, n);
    }
}

// round 7
// speedup vs baseline: 1.7038x; 1.7038x over previous
#include <cuda_runtime.h>
#include <math.h>
#include <cstdint>

#define NN 50000
#define NE 800000
#define CH 64
#define SEQL 8
#define KB 192

// ---------------- static scratch ----------------
__device__ float g_deg[NN];
__device__ float g_dinv[NN];
__device__ int   g_cnt[NN];
__device__ int   g_off[NN + 1];
__device__ int   g_cur[NN];
__device__ int   g_col[NE];
__device__ float g_w[NE];
__device__ float g_XB[(size_t)NN * KB];     // basis buffer [N][192] (reused X/H/HR)
__device__ float g_GX[(size_t)NN * KB];     // x-gate preactivations [N][192]
__device__ float g_Z [(size_t)NN * CH];
__device__ float g_HR[(size_t)NN * CH];
__device__ float g_H0[(size_t)NN * CH];     // stays zero
__device__ float g_BX [192 * KB];           // transposed weights [n_out][k]
__device__ float g_BZR[128 * KB];
__device__ float g_BH [64 * KB];
__device__ float g_bX [192];
__device__ float g_bZR[128];

// ---------------- setup kernels ----------------
__global__ void k_zero_setup() {
    int i = blockIdx.x * blockDim.x + threadIdx.x;
    if (i < NN) { g_deg[i] = 0.f; g_cnt[i] = 0; g_cur[i] = 0; }
}
__global__ void k_deg(const int* __restrict__ ei, const float* __restrict__ ew) {
    int e = blockIdx.x * blockDim.x + threadIdx.x;
    if (e < NE) {
        int r = ei[e], c = ei[NE + e];
        if (r != c) atomicAdd(&g_deg[r], ew[e]);
    }
}
__global__ void k_dinv() {
    int i = blockIdx.x * blockDim.x + threadIdx.x;
    if (i < NN) {
        float d = g_deg[i];
        g_dinv[i] = d > 0.f ? rsqrtf(d) : 0.f;
    }
}
__global__ void k_count(const int* __restrict__ ei) {
    int e = blockIdx.x * blockDim.x + threadIdx.x;
    if (e < NE) atomicAdd(&g_cnt[ei[e]], 1);
}
__global__ void k_scan() {
    __shared__ int sh[1024];
    int tid = threadIdx.x;
    const int chunk = (NN + 1023) / 1024;
    int base = tid * chunk, s = 0;
    for (int i = 0; i < chunk; i++) { int idx = base + i; if (idx < NN) s += g_cnt[idx]; }
    sh[tid] = s;
    __syncthreads();
    for (int d = 1; d < 1024; d <<= 1) {
        int v = (tid >= d) ? sh[tid - d] : 0;
        __syncthreads(); sh[tid] += v; __syncthreads();
    }
    int run = (tid == 0) ? 0 : sh[tid - 1];
    for (int i = 0; i < chunk; i++) {
        int idx = base + i;
        if (idx < NN) { g_off[idx] = run; run += g_cnt[idx]; }
    }
    if (tid == 0) g_off[NN] = sh[1023];
}
__global__ void k_scatter(const int* __restrict__ ei, const float* __restrict__ ew) {
    int e = blockIdx.x * blockDim.x + threadIdx.x;
    if (e < NE) {
        int r = ei[e], c = ei[NE + e];
        float w = (r == c) ? 0.f : ew[e];
        float wn = -w * g_dinv[r] * g_dinv[c];
        int pos = g_off[r] + atomicAdd(&g_cur[r], 1);
        g_col[pos] = c; g_w[pos] = wn;
    }
}
// build transposed weight matrices B[n_out][k] with k = cheb*64+cin; concat biases
__global__ void k_prepB(const float* __restrict__ Wxz, const float* __restrict__ Wxr,
                        const float* __restrict__ Wxh, const float* __restrict__ Whz,
                        const float* __restrict__ Whr, const float* __restrict__ Whh,
                        const float* __restrict__ bxz, const float* __restrict__ bxr,
                        const float* __restrict__ bxh, const float* __restrict__ bhz,
                        const float* __restrict__ bhr) {
    int i = blockIdx.x * blockDim.x + threadIdx.x;
    if (i < 192 * KB) {
        int n = i / KB, k = i % KB, kc = k / 64, ci = k & 63, gate = n / 64, c = n & 63;
        const float* W = gate == 0 ? Wxz : (gate == 1 ? Wxr : Wxh);
        g_BX[i] = W[kc * 4096 + ci * 64 + c];
    }
    if (i < 128 * KB) {
        int n = i / KB, k = i % KB, kc = k / 64, ci = k & 63, c = n & 63;
        const float* W = n < 64 ? Whz : Whr;
        g_BZR[i] = W[kc * 4096 + ci * 64 + c];
    }
    if (i < 64 * KB) {
        int n = i / KB, k = i % KB, kc = k / 64, ci = k & 63;
        g_BH[i] = Whh[kc * 4096 + ci * 64 + (n & 63)];
    }
    if (i < 192) g_bX[i] = i < 64 ? bxz[i] : (i < 128 ? bxr[i - 64] : bxh[i - 128]);
    if (i < 128) g_bZR[i] = i < 64 ? bhz[i] : bhr[i - 64];
}

// ---------------- SpMM into basis buffer ----------------
__global__ void k_spmmA(const float* __restrict__ v, int vs, float* __restrict__ XB) {
    int warp = (blockIdx.x * blockDim.x + threadIdx.x) >> 5;
    int lane = threadIdx.x & 31;
    if (warp >= NN) return;
    int s = g_off[warp], e = g_off[warp + 1];
    float a0 = 0.f, a1 = 0.f, b0 = 0.f, b1 = 0.f;
    int j = s;
    for (; j + 1 < e; j += 2) {
        int c0 = g_col[j], c1 = g_col[j + 1];
        float w0 = g_w[j], w1 = g_w[j + 1];
        const float* p0 = v + (size_t)c0 * vs;
        const float* p1 = v + (size_t)c1 * vs;
        a0 += w0 * p0[lane];  a1 += w0 * p0[lane + 32];
        b0 += w1 * p1[lane];  b1 += w1 * p1[lane + 32];
    }
    if (j < e) {
        int c = g_col[j]; float w = g_w[j];
        const float* p = v + (size_t)c * vs;
        a0 += w * p[lane]; a1 += w * p[lane + 32];
    }
    size_t o = (size_t)warp * KB;
    const float* pr = v + (size_t)warp * vs;
    XB[o + lane]       = pr[lane];
    XB[o + lane + 32]  = pr[lane + 32];
    XB[o + 64 + lane]  = a0 + b0;
    XB[o + 96 + lane]  = a1 + b1;
}
__global__ void k_spmmB(float* __restrict__ XB) {
    int warp = (blockIdx.x * blockDim.x + threadIdx.x) >> 5;
    int lane = threadIdx.x & 31;
    if (warp >= NN) return;
    int s = g_off[warp], e = g_off[warp + 1];
    float a0 = 0.f, a1 = 0.f, b0 = 0.f, b1 = 0.f;
    int j = s;
    for (; j + 1 < e; j += 2) {
        int c0 = g_col[j], c1 = g_col[j + 1];
        float w0 = g_w[j], w1 = g_w[j + 1];
        const float* p0 = XB + (size_t)c0 * KB + 64;
        const float* p1 = XB + (size_t)c1 * KB + 64;
        a0 += w0 * p0[lane];  a1 += w0 * p0[lane + 32];
        b0 += w1 * p1[lane];  b1 += w1 * p1[lane + 32];
    }
    if (j < e) {
        int c = g_col[j]; float w = g_w[j];
        const float* p = XB + (size_t)c * KB + 64;
        a0 += w * p[lane]; a1 += w * p[lane + 32];
    }
    size_t o = (size_t)warp * KB;
    XB[o + 128 + lane] = 2.f * (a0 + b0) - XB[o + lane];
    XB[o + 160 + lane] = 2.f * (a1 + b1) - XB[o + lane + 32];
}

// ---------------- tf32 mma.sync GEMM, fused epilogues ----------------
__device__ __forceinline__ uint32_t f2tf32(float f) {
    uint32_t u;
    asm("cvt.rna.tf32.f32 %0, %1;" : "=r"(u) : "f"(f));
    return u;
}
__device__ __forceinline__ void mma_tf32(float* d, const uint32_t* a, const uint32_t* b) {
    asm volatile(
        "mma.sync.aligned.m16n8k8.row.col.f32.tf32.tf32.f32 "
        "{%0,%1,%2,%3}, {%4,%5,%6,%7}, {%8,%9}, {%0,%1,%2,%3};\n"
        : "+f"(d[0]), "+f"(d[1]), "+f"(d[2]), "+f"(d[3])
        : "r"(a[0]), "r"(a[1]), "r"(a[2]), "r"(a[3]), "r"(b[0]), "r"(b[1]));
}

// D[128 x NOUT] = A[128 x 192] @ B[NOUT x 192]^T
// EPI 0: out[r*192+c] = acc + bias                                   (GX)
// EPI 1: c<64: Z = sigmoid(acc+bias+GX[r,c]); c>=64: HR = H[r,c-64]*sigmoid(...)
// EPI 2: Ht = tanh(acc+bias+GX[r,128+c]); out = Z*H + (1-Z)*Ht       (States)
#define PADK 36

template <int NOUT, int EPI>
__global__ void __launch_bounds__(128 * (NOUT / 64)) k_mgemm(
    const float* __restrict__ A, const float* __restrict__ B,
    const float* __restrict__ bias, const float* __restrict__ GX,
    const float* __restrict__ H, const float* __restrict__ Z,
    float* __restrict__ out, float* __restrict__ out2, int rows)
{
    __shared__ uint32_t As[128 * PADK];
    __shared__ uint32_t Bs[NOUT * PADK];

    const int NTH = 128 * (NOUT / 64);
    int tid = threadIdx.x;
    int wid = tid >> 5, lane = tid & 31;
    int mw = wid & 3;          // M warp group: rows mw*32..+31
    int nw = wid >> 2;         // N warp group: cols nw*64..+63
    int rb = blockIdx.x * 128;

    float acc[2][8][4];
#pragma unroll
    for (int mt = 0; mt < 2; mt++)
#pragma unroll
        for (int nt = 0; nt < 8; nt++)
#pragma unroll
            for (int q = 0; q < 4; q++) acc[mt][nt][q] = 0.f;

    for (int kc = 0; kc < 6; kc++) {
        // stage A tile: 128 rows x 32 k (1024 float4 slots) — grid-stride, covers all
#pragma unroll
        for (int idx = tid; idx < 1024; idx += NTH) {
            int row = idx >> 3, q = idx & 7;
            float4 v = make_float4(0.f, 0.f, 0.f, 0.f);
            int gr = rb + row;
            if (gr < rows) v = *(const float4*)(A + (size_t)gr * KB + kc * 32 + q * 4);
            uint32_t* p = &As[row * PADK + q * 4];
            p[0] = f2tf32(v.x); p[1] = f2tf32(v.y); p[2] = f2tf32(v.z); p[3] = f2tf32(v.w);
        }
        // stage B tile: NOUT rows x 32 k (NOUT*8 float4 slots)
#pragma unroll
        for (int idx = tid; idx < NOUT * 8; idx += NTH) {
            int row = idx >> 3, q = idx & 7;
            float4 v = *(const float4*)(B + (size_t)row * KB + kc * 32 + q * 4);
            uint32_t* p = &Bs[row * PADK + q * 4];
            p[0] = f2tf32(v.x); p[1] = f2tf32(v.y); p[2] = f2tf32(v.z); p[3] = f2tf32(v.w);
        }
        __syncthreads();
#pragma unroll
        for (int kk = 0; kk < 4; kk++) {
            uint32_t a[2][4];
#pragma unroll
            for (int mt = 0; mt < 2; mt++) {
                int r = mw * 32 + mt * 16 + (lane >> 2);
                int c = kk * 8 + (lane & 3);
                a[mt][0] = As[r * PADK + c];
                a[mt][1] = As[(r + 8) * PADK + c];
                a[mt][2] = As[r * PADK + c + 4];
                a[mt][3] = As[(r + 8) * PADK + c + 4];
            }
            uint32_t b[8][2];
#pragma unroll
            for (int nt = 0; nt < 8; nt++) {
                int n = nw * 64 + nt * 8 + (lane >> 2);
                int c = kk * 8 + (lane & 3);
                b[nt][0] = Bs[n * PADK + c];
                b[nt][1] = Bs[n * PADK + c + 4];
            }
#pragma unroll
            for (int mt = 0; mt < 2; mt++)
#pragma unroll
                for (int nt = 0; nt < 8; nt++)
                    mma_tf32(acc[mt][nt], a[mt], b[nt]);
        }
        __syncthreads();
    }

    // epilogue: each thread owns float2 at (r, c) and (r+8, c) per tile
#pragma unroll
    for (int mt = 0; mt < 2; mt++) {
#pragma unroll
        for (int nt = 0; nt < 8; nt++) {
            int c = nw * 64 + nt * 8 + (lane & 3) * 2;
            float bx = bias[c], by = bias[c + 1];
#pragma unroll
            for (int hh = 0; hh < 2; hh++) {
                int r = rb + mw * 32 + mt * 16 + (lane >> 2) + hh * 8;
                if (r >= rows) continue;
                float vx = acc[mt][nt][hh * 2] + bx;
                float vy = acc[mt][nt][hh * 2 + 1] + by;
                if (EPI == 0) {
                    *(float2*)(out + (size_t)r * KB + c) = make_float2(vx, vy);
                } else if (EPI == 1) {
                    float2 gx = *(const float2*)(GX + (size_t)r * KB + c);
                    float sx = 1.f / (1.f + expf(-(vx + gx.x)));
                    float sy = 1.f / (1.f + expf(-(vy + gx.y)));
                    if (c < 64) {
                        *(float2*)(out + (size_t)r * CH + c) = make_float2(sx, sy);
                    } else {
                        float2 h = *(const float2*)(H + (size_t)r * CH + (c - 64));
                        *(float2*)(out2 + (size_t)r * CH + (c - 64)) =
                            make_float2(h.x * sx, h.y * sy);
                    }
                } else {
                    float2 gx = *(const float2*)(GX + (size_t)r * KB + 128 + c);
                    float2 h  = *(const float2*)(H + (size_t)r * CH + c);
                    float2 z2 = *(const float2*)(Z + (size_t)r * CH + c);
                    float tx = tanhf(vx + gx.x), ty = tanhf(vy + gx.y);
                    *(float2*)(out + (size_t)r * CH + c) = make_float2(
                        z2.x * h.x + (1.f - z2.x) * tx,
                        z2.y * h.y + (1.f - z2.y) * ty);
                }
            }
        }
    }
}

__global__ void k_copy(const float* __restrict__ src, float* __restrict__ dst, int n) {
    int i = blockIdx.x * blockDim.x + threadIdx.x;
    if (i < n) dst[i] = src[i];
}

// ---------------- host side ----------------
extern "C" void kernel_launch(void* const* d_in, const int* in_sizes, int n_in,
                              void* d_out, int out_size) {
    const float* X    = (const float*)d_in[0];
    const int*   ei   = (const int*)  d_in[1];
    const float* ew   = (const float*)d_in[2];
    const float* W_xz = (const float*)d_in[3];
    const float* b_xz = (const float*)d_in[4];
    const float* W_hz = (const float*)d_in[5];
    const float* b_hz = (const float*)d_in[6];
    const float* W_xr = (const float*)d_in[7];
    const float* b_xr = (const float*)d_in[8];
    const float* W_hr = (const float*)d_in[9];
    const float* b_hr = (const float*)d_in[10];
    const float* W_xh = (const float*)d_in[11];
    const float* b_xh = (const float*)d_in[12];
    const float* W_hh = (const float*)d_in[13];
    const float* b_hh = (const float*)d_in[14];
    float* out = (float*)d_out;

    float *pXB, *pGX, *pZ, *pHR, *pH0, *pBX, *pBZR, *pBH, *pbX, *pbZR;
    cudaGetSymbolAddress((void**)&pXB, g_XB);
    cudaGetSymbolAddress((void**)&pGX, g_GX);
    cudaGetSymbolAddress((void**)&pZ,  g_Z);
    cudaGetSymbolAddress((void**)&pHR, g_HR);
    cudaGetSymbolAddress((void**)&pH0, g_H0);
    cudaGetSymbolAddress((void**)&pBX, g_BX);
    cudaGetSymbolAddress((void**)&pBZR, g_BZR);
    cudaGetSymbolAddress((void**)&pBH, g_BH);
    cudaGetSymbolAddress((void**)&pbX, g_bX);
    cudaGetSymbolAddress((void**)&pbZR, g_bZR);

    const int NB_NODE = (NN + 255) / 256;
    const int NB_EDGE = (NE + 255) / 256;
    const int NB_SPMM = (NN * 32 + 255) / 256;
    const int NB_GEMM = (NN + 127) / 128;

    k_zero_setup<<<NB_NODE, 256>>>();
    k_deg<<<NB_EDGE, 256>>>(ei, ew);
    k_dinv<<<NB_NODE, 256>>>();
    k_count<<<NB_EDGE, 256>>>(ei);
    k_scan<<<1, 1024>>>();
    k_scatter<<<NB_EDGE, 256>>>(ei, ew);
    k_prepB<<<(192 * KB + 255) / 256, 256>>>(W_xz, W_xr, W_xh, W_hz, W_hr, W_hh,
                                             b_xz, b_xr, b_xh, b_hz, b_hr);

    const size_t SL = (size_t)NN * CH;

    for (int t = 0; t < SEQL; t++) {
        const float* Xt = X + (size_t)t * SL;
        const float* Hp = (t == 0) ? pH0 : (out + (size_t)(t - 1) * SL);
        float* Ot = out + (size_t)t * SL;

        // X basis -> GX (three x-gates fused, N=192)
        k_spmmA<<<NB_SPMM, 256>>>(Xt, CH, pXB);
        k_spmmB<<<NB_SPMM, 256>>>(pXB);
        k_mgemm<192, 0><<<NB_GEMM, 384>>>(pXB, pBX, pbX, nullptr, nullptr,
                                          nullptr, pGX, nullptr, NN);
        // H basis -> Z, HR (z+r fused, N=128)
        k_spmmA<<<NB_SPMM, 256>>>(Hp, CH, pXB);
        k_spmmB<<<NB_SPMM, 256>>>(pXB);
        k_mgemm<128, 1><<<NB_GEMM, 256>>>(pXB, pBZR, pbZR, pGX, Hp,
                                          nullptr, pZ, pHR, NN);
        // HR basis -> candidate + GRU combine -> States[t]
        k_spmmA<<<NB_SPMM, 256>>>(pHR, CH, pXB);
        k_spmmB<<<NB_SPMM, 256>>>(pXB);
        k_mgemm<64, 2><<<NB_GEMM, 128>>>(pXB, pBH, b_hh, pGX, Hp,
                                         pZ, Ot, nullptr, NN);
    }

    if (out_size >= (int)((SEQL + 1) * SL)) {
        int n = (int)SL;
        k_copy<<<(n + 255) / 256, 256>>>(out + (size_t)(SEQL - 1) * SL,
                                         out + (size_t)SEQL * SL, n);
    }
}